// round 14
// baseline (speedup 1.0000x reference)
#include <cuda_runtime.h>
#include <math.h>
#include <stdint.h>

#define Bn 256
#define Tn 512
#define Fn 16
#define Hn 256
#define Gcols 1024       // interleaved gate cols: unit*4 + gate (i,f,g,o)
#define CLSZ 8           // CTAs per cluster (unit-split)
#define BT 16            // batches per cluster group
#define NGRP (Bn/BT)     // 16 groups
#define UPC (Hn/CLSZ)    // 32 units per CTA

typedef unsigned long long u64;

// ---- scratch (__device__ globals; no allocation allowed) ----
__device__ float g_Wih0i[Fn*Gcols];        // [k][u4g] interleaved
__device__ float g_Whh0i[Hn*Gcols];
__device__ float g_Wih1i[Hn*Gcols];
__device__ float g_Whh1i[Hn*Gcols];
__device__ float g_b0i[Gcols], g_b1i[Gcols];
__device__ float g_h0out[(size_t)Bn*Tn*Hn];       // [b][t][u] (rows of 256)
__device__ float g_XP0[(size_t)Bn*Tn*Gcols];      // interleaved gate addends
__device__ float g_XP1[(size_t)Bn*Tn*Gcols];
__device__ float g_hlast[Bn*Hn];

// ---------------- helpers ----------------
__device__ __forceinline__ u64 pack2(float a, float b) {
    u64 r; asm("mov.b64 %0, {%1, %2};" : "=l"(r) : "f"(a), "f"(b)); return r;
}
__device__ __forceinline__ void unpack2(u64 v, float& a, float& b) {
    asm("mov.b64 {%0, %1}, %2;" : "=f"(a), "=f"(b) : "l"(v));
}
__device__ __forceinline__ void ffma2(u64& acc, u64 a, u64 b) {
    asm("fma.rn.f32x2 %0, %1, %2, %0;" : "+l"(acc) : "l"(a), "l"(b));
}
__device__ __forceinline__ float fast_sigmoid(float x) {
    return 1.f / (1.f + __expf(-x));
}
__device__ __forceinline__ float fast_tanh(float x) {
    return 1.f - 2.f / (1.f + __expf(2.f * x));
}
__device__ __forceinline__ uint32_t ctarank() {
    uint32_t r; asm("mov.u32 %0, %%cluster_ctarank;" : "=r"(r)); return r;
}
__device__ __forceinline__ void cluster_sync() {
    asm volatile("barrier.cluster.arrive.aligned;" ::: "memory");
    asm volatile("barrier.cluster.wait.aligned;"   ::: "memory");
}
__device__ __forceinline__ void st_cluster_u64(uint32_t laddr, uint32_t rank, u64 v) {
    asm volatile(
        "{ .reg .b32 ra;\n\t"
        "  mapa.shared::cluster.u32 ra, %0, %1;\n\t"
        "  st.shared::cluster.u64 [ra], %2; }"
        :: "r"(laddr), "r"(rank), "l"(v) : "memory");
}
__device__ __forceinline__ void cp16(uint32_t dst_smem, const void* src) {
    asm volatile("cp.async.cg.shared.global [%0], [%1], 16;"
                 :: "r"(dst_smem), "l"(src) : "memory");
}
__device__ __forceinline__ void cp_commit() {
    asm volatile("cp.async.commit_group;" ::: "memory");
}
template<int N> __device__ __forceinline__ void cp_wait() {
    asm volatile("cp.async.wait_group %0;" :: "n"(N) : "memory");
}

// ---------------- prep: transpose + interleave all weights ----------------
__global__ void prep_kernel(const float* __restrict__ wih0, const float* __restrict__ whh0,
                            const float* __restrict__ bih0, const float* __restrict__ bhh0,
                            const float* __restrict__ wih1, const float* __restrict__ whh1,
                            const float* __restrict__ bih1, const float* __restrict__ bhh1) {
    int idx = blockIdx.x * blockDim.x + threadIdx.x;
    int stride = gridDim.x * blockDim.x;
    for (int i = idx; i < Fn*Gcols; i += stride) {
        int k = i >> 10, col = i & 1023, u = col >> 2, g = col & 3;
        g_Wih0i[i] = wih0[(g*Hn + u)*Fn + k];
    }
    for (int i = idx; i < Hn*Gcols; i += stride) {
        int k = i >> 10, col = i & 1023, u = col >> 2, g = col & 3;
        int jo = g*Hn + u;
        g_Whh0i[i] = whh0[jo*Hn + k];
        g_Wih1i[i] = wih1[jo*Hn + k];
        g_Whh1i[i] = whh1[jo*Hn + k];
    }
    for (int col = idx; col < Gcols; col += stride) {
        int u = col >> 2, g = col & 3, jo = g*Hn + u;
        g_b0i[col] = bih0[jo] + bhh0[jo];
        g_b1i[col] = bih1[jo] + bhh1[jo];
    }
}

// ---------------- xp0: XP0[row][col] = b0 + W_ih0 . x_row  (K=16) ----------------
__global__ __launch_bounds__(256, 1)
void xp0_kernel(const float* __restrict__ x) {
    __shared__ float xs[8][Fn];
    const int tid = threadIdx.x;
    const size_t row0 = (size_t)blockIdx.x * 8;
    if (tid < 8*Fn) xs[tid >> 4][tid & 15] = x[row0*Fn + tid];
    __syncthreads();
    const int col4 = tid * 4;
    const u64 b01 = *reinterpret_cast<const u64*>(g_b0i + col4);
    const u64 b23 = *reinterpret_cast<const u64*>(g_b0i + col4 + 2);
    u64 acc[8][2];
    #pragma unroll
    for (int r = 0; r < 8; ++r) { acc[r][0] = b01; acc[r][1] = b23; }
    #pragma unroll
    for (int k = 0; k < Fn; ++k) {
        float4 w = *reinterpret_cast<const float4*>(g_Wih0i + k*Gcols + col4);
        u64 w01 = pack2(w.x, w.y), w23 = pack2(w.z, w.w);
        #pragma unroll
        for (int r = 0; r < 8; ++r) {
            u64 xx = pack2(xs[r][k], xs[r][k]);
            ffma2(acc[r][0], w01, xx);
            ffma2(acc[r][1], w23, xx);
        }
    }
    #pragma unroll
    for (int r = 0; r < 8; ++r) {
        float o0,o1,o2,o3;
        unpack2(acc[r][0], o0, o1); unpack2(acc[r][1], o2, o3);
        *reinterpret_cast<float4*>(g_XP0 + (row0 + r)*Gcols + col4)
            = make_float4(o0, o1, o2, o3);
    }
}

// ---------------- xp1: XP1 = b1 + h0 @ Wih1i   (M=131072, N=1024, K=256) ----------
#define BM 64
#define BN 128
#define BK 32
__global__ __launch_bounds__(256, 1)
void xp1_gemm() {
    __shared__ float As[2][BK][BM];   // 16384 B
    __shared__ float Bs[2][BK][BN];   // 32768 B  (total 49152 = 48KB)
    const int tid = threadIdx.x;
    const size_t row0 = (size_t)blockIdx.x * BM;
    const int n0 = blockIdx.y * BN;
    const int tm = tid >> 4, tn = tid & 15;     // 16 x 16
    const int mA = tid >> 2, kq = tid & 3;      // A loader: row mA, k-block kq*8

    const float* Aptr = g_h0out + (row0 + mA)*Hn + kq*8;
    const uint32_t bs_s = (uint32_t)__cvta_generic_to_shared(&Bs[0][0][0]);

    u64 acc[4][4];
    #pragma unroll
    for (int i = 0; i < 4; ++i)
        #pragma unroll
        for (int j = 0; j < 4; ++j) acc[i][j] = 0ull;

    // preload stage 0
    float4 a0 = *reinterpret_cast<const float4*>(Aptr);
    float4 a1 = *reinterpret_cast<const float4*>(Aptr + 4);
    #pragma unroll
    for (int j = 0; j < 4; ++j) {
        int c = tid + 256*j, kB = c >> 5, nB = (c & 31)*4;
        cp16(bs_s + (size_t)(kB*BN + nB)*4,
             g_Wih1i + (size_t)kB*Gcols + n0 + nB);
    }
    cp_commit();
    As[0][kq*8+0][mA] = a0.x; As[0][kq*8+1][mA] = a0.y;
    As[0][kq*8+2][mA] = a0.z; As[0][kq*8+3][mA] = a0.w;
    As[0][kq*8+4][mA] = a1.x; As[0][kq*8+5][mA] = a1.y;
    As[0][kq*8+6][mA] = a1.z; As[0][kq*8+7][mA] = a1.w;
    cp_wait<0>();
    __syncthreads();

    for (int s = 0; s < Hn/BK; ++s) {
        const int buf = s & 1, nxt = buf ^ 1;
        if (s < Hn/BK - 1) {
            const int kk = (s+1)*BK;
            #pragma unroll
            for (int j = 0; j < 4; ++j) {
                int c = tid + 256*j, kB = c >> 5, nB = (c & 31)*4;
                cp16(bs_s + ((size_t)nxt*BK*BN + kB*BN + nB)*4,
                     g_Wih1i + (size_t)(kk + kB)*Gcols + n0 + nB);
            }
            cp_commit();
            a0 = *reinterpret_cast<const float4*>(Aptr + kk);
            a1 = *reinterpret_cast<const float4*>(Aptr + kk + 4);
        }
        #pragma unroll
        for (int k = 0; k < BK; ++k) {
            float4 av = *reinterpret_cast<const float4*>(&As[buf][k][tm*4]);
            const u64* bp = reinterpret_cast<const u64*>(&Bs[buf][k][tn*8]);
            u64 bv0 = bp[0], bv1 = bp[1], bv2 = bp[2], bv3 = bp[3];
            u64 am0 = pack2(av.x, av.x), am1 = pack2(av.y, av.y);
            u64 am2 = pack2(av.z, av.z), am3 = pack2(av.w, av.w);
            ffma2(acc[0][0], bv0, am0); ffma2(acc[0][1], bv1, am0);
            ffma2(acc[0][2], bv2, am0); ffma2(acc[0][3], bv3, am0);
            ffma2(acc[1][0], bv0, am1); ffma2(acc[1][1], bv1, am1);
            ffma2(acc[1][2], bv2, am1); ffma2(acc[1][3], bv3, am1);
            ffma2(acc[2][0], bv0, am2); ffma2(acc[2][1], bv1, am2);
            ffma2(acc[2][2], bv2, am2); ffma2(acc[2][3], bv3, am2);
            ffma2(acc[3][0], bv0, am3); ffma2(acc[3][1], bv1, am3);
            ffma2(acc[3][2], bv2, am3); ffma2(acc[3][3], bv3, am3);
        }
        if (s < Hn/BK - 1) {
            cp_wait<0>();
            As[nxt][kq*8+0][mA] = a0.x; As[nxt][kq*8+1][mA] = a0.y;
            As[nxt][kq*8+2][mA] = a0.z; As[nxt][kq*8+3][mA] = a0.w;
            As[nxt][kq*8+4][mA] = a1.x; As[nxt][kq*8+5][mA] = a1.y;
            As[nxt][kq*8+6][mA] = a1.z; As[nxt][kq*8+7][mA] = a1.w;
            __syncthreads();
        }
    }
    // epilogue: add bias, store
    const float* bb = g_b1i + n0 + tn*8;
    float bias[8];
    #pragma unroll
    for (int j = 0; j < 8; ++j) bias[j] = bb[j];
    #pragma unroll
    for (int mi = 0; mi < 4; ++mi) {
        float o[8];
        unpack2(acc[mi][0], o[0], o[1]); unpack2(acc[mi][1], o[2], o[3]);
        unpack2(acc[mi][2], o[4], o[5]); unpack2(acc[mi][3], o[6], o[7]);
        float* dst = g_XP1 + (row0 + tm*4 + mi)*Gcols + n0 + tn*8;
        *reinterpret_cast<float4*>(dst)     = make_float4(o[0]+bias[0], o[1]+bias[1],
                                                          o[2]+bias[2], o[3]+bias[3]);
        *reinterpret_cast<float4*>(dst + 4) = make_float4(o[4]+bias[4], o[5]+bias[5],
                                                          o[6]+bias[6], o[7]+bias[7]);
    }
}

// ---------------- recurrence: smem-resident Whh, 8-CTA cluster, DSMEM h ----------
// 128 CTAs = 16 groups x 8 ranks. Group owns 16 batches; rank owns 32 units.
// Thread: u = tid>>3 (local unit), q = tid&7 -> batches {2q, 2q+1}.
// smem: ws[256][128] = this rank's Whh slice (loaded ONCE);
//       v2[2][256][16] u64 packed (h,h), parity double-buffered.
// XP selected INSIDE the kernel (device symbol — never pass from host!).
template<int LAYER>
__global__ __launch_bounds__(256, 1) __cluster_dims__(CLSZ, 1, 1)
void lstm_recur(const int* __restrict__ lengths) {
    extern __shared__ __align__(16) char smem[];
    u64*   v2 = reinterpret_cast<u64*>(smem);                 // [2][256][16]
    float* ws = reinterpret_cast<float*>(smem + 2*Hn*BT*8);   // [256][128]
    __shared__ int len_sh[BT];

    const float* __restrict__ Whh = LAYER ? g_Whh1i : g_Whh0i;
    const float* __restrict__ XP  = LAYER ? g_XP1  : g_XP0;   // device-side select

    const int tid = threadIdx.x;
    const int u   = tid >> 3;          // 0..31
    const int q   = tid & 7;           // 0..7 -> batches 2q,2q+1
    const int grp = blockIdx.x >> 3;
    const uint32_t rank = ctarank();
    const int b0g = grp * BT;
    const int unit = (int)rank * UPC + u;

    if (tid < BT) len_sh[tid] = lengths[b0g + tid];
    // zero both parity planes
    for (int i = tid; i < 2*Hn*BT; i += 256) v2[i] = 0ull;
    // load this rank's Whh slice: ws[k][c] = Whh[k*1024 + rank*128 + c]
    {
        const int base = (int)rank * 128;
        for (int it = 0; it < 32; ++it) {
            int idx4 = tid*4 + it*1024;
            int k = idx4 >> 7, c = idx4 & 127;
            *reinterpret_cast<float4*>(ws + idx4) =
                *reinterpret_cast<const float4*>(Whh + (size_t)k*Gcols + base + c);
        }
    }
    __syncthreads();
    cluster_sync();   // all CTAs zeroed before any DSMEM pushes arrive

    const uint32_t v2_s = (uint32_t)__cvta_generic_to_shared(v2);
    const float* xpA = XP + (size_t)(b0g + 2*q)     * Tn * Gcols + unit*4;
    const float* xpB = XP + (size_t)(b0g + 2*q + 1) * Tn * Gcols + unit*4;
    float4 xa = *reinterpret_cast<const float4*>(xpA);
    float4 xb = *reinterpret_cast<const float4*>(xpB);

    float c0 = 0.f, c1 = 0.f;
    int par = 0;

    for (int t = 0; t < Tn; ++t) {
        u64 a01_0 = pack2(xa.x, xa.y), a23_0 = pack2(xa.z, xa.w);
        u64 a01_1 = pack2(xb.x, xb.y), a23_1 = pack2(xb.z, xb.w);
        if (t + 1 < Tn) {   // prefetch next step's XP (hidden under gate loop)
            xa = *reinterpret_cast<const float4*>(xpA + (size_t)(t+1)*Gcols);
            xb = *reinterpret_cast<const float4*>(xpB + (size_t)(t+1)*Gcols);
        }

        const u64*   vb = v2 + (size_t)par*Hn*BT + q*2;
        const float* wb = ws + u*4;
        #pragma unroll 8
        for (int k = 0; k < Hn; ++k) {
            const ulonglong2 w = *reinterpret_cast<const ulonglong2*>(wb + k*128);
            const ulonglong2 p = *reinterpret_cast<const ulonglong2*>(vb + k*BT);
            ffma2(a01_0, w.x, p.x); ffma2(a23_0, w.y, p.x);
            ffma2(a01_1, w.x, p.y); ffma2(a23_1, w.y, p.y);
        }

        // ---- update (gate order i,f,g,o) ----
        float ig, fg, gg, og, h0v, h1v;
        unpack2(a01_0, ig, fg); unpack2(a23_0, gg, og);
        c0 = fast_sigmoid(fg) * c0 + fast_sigmoid(ig) * fast_tanh(gg);
        h0v = fast_sigmoid(og) * fast_tanh(c0);
        unpack2(a01_1, ig, fg); unpack2(a23_1, gg, og);
        c1 = fast_sigmoid(fg) * c1 + fast_sigmoid(ig) * fast_tanh(gg);
        h1v = fast_sigmoid(og) * fast_tanh(c1);

        // ---- DSMEM broadcast into every rank's v2[par^1] ----
        const uint32_t dst = v2_s
            + (uint32_t)((((par ^ 1)*Hn + unit)*BT + q*2) * 8);
        const u64 hx0 = pack2(h0v, h0v), hx1 = pack2(h1v, h1v);
        #pragma unroll
        for (uint32_t rk = 0; rk < CLSZ; ++rk) {
            st_cluster_u64(dst,     rk, hx0);
            st_cluster_u64(dst + 8, rk, hx1);
        }

        if (LAYER == 0) {
            g_h0out[((size_t)(b0g + 2*q)   * Tn + t) * Hn + unit] = h0v;
            g_h0out[((size_t)(b0g + 2*q+1) * Tn + t) * Hn + unit] = h1v;
        } else {
            if (t == len_sh[2*q]   - 1) g_hlast[(b0g + 2*q)  *Hn + unit] = h0v;
            if (t == len_sh[2*q+1] - 1) g_hlast[(b0g + 2*q+1)*Hn + unit] = h1v;
        }

        cluster_sync();   // release pushes / acquire peers'
        par ^= 1;
    }
}

// ---------------- final: relu(hlast) @ fc_w^T + fc_b ----------------
__global__ void final_kernel(const float* __restrict__ fc_w, const float* __restrict__ fc_b,
                             float* __restrict__ out) {
    __shared__ float red[256];
    int b = blockIdx.x, u = threadIdx.x;
    float v = fmaxf(g_hlast[b * Hn + u], 0.f) * fc_w[u];
    red[u] = v;
    __syncthreads();
    #pragma unroll
    for (int s = 128; s > 0; s >>= 1) {
        if (u < s) red[u] += red[u + s];
        __syncthreads();
    }
    if (u == 0) out[b] = red[0] + fc_b[0];
}

extern "C" void kernel_launch(void* const* d_in, const int* in_sizes, int n_in,
                              void* d_out, int out_size) {
    const float* x    = (const float*)d_in[0];
    const int*   lens = (const int*)  d_in[1];
    const float* wih0 = (const float*)d_in[2];
    const float* whh0 = (const float*)d_in[3];
    const float* bih0 = (const float*)d_in[4];
    const float* bhh0 = (const float*)d_in[5];
    const float* wih1 = (const float*)d_in[6];
    const float* whh1 = (const float*)d_in[7];
    const float* bih1 = (const float*)d_in[8];
    const float* bhh1 = (const float*)d_in[9];
    const float* fcw  = (const float*)d_in[10];
    const float* fcb  = (const float*)d_in[11];
    float* out = (float*)d_out;

    const int smemR = 2*Hn*BT*8 + Hn*128*4;   // 65536 + 131072 = 196608
    cudaFuncSetAttribute(lstm_recur<0>,
                         cudaFuncAttributeMaxDynamicSharedMemorySize, smemR);
    cudaFuncSetAttribute(lstm_recur<1>,
                         cudaFuncAttributeMaxDynamicSharedMemorySize, smemR);

    prep_kernel<<<148, 256>>>(wih0, whh0, bih0, bhh0, wih1, whh1, bih1, bhh1);
    xp0_kernel<<<(Bn*Tn)/8, 256>>>(x);
    lstm_recur<0><<<NGRP*CLSZ, 256, smemR>>>(lens);
    xp1_gemm<<<dim3((Bn*Tn)/BM, Gcols/BN), 256>>>();
    lstm_recur<1><<<NGRP*CLSZ, 256, smemR>>>(lens);
    final_kernel<<<Bn, 256>>>(fcw, fcb, out);
}